// round 10
// baseline (speedup 1.0000x reference)
#include <cuda_runtime.h>
#include <cstdint>

#define Nn 8
#define Cc 128
#define Ll 1024
#define Kk 100
#define EPSf 1e-8f

// Normalized fp32 rows, [N, L, C] (512B per row).
__device__ float g_zf[Nn * Ll * Cc];
__device__ float g_cf[Nn * Ll * Cc];

// Fused: transpose + norm + normalize, one pass over the input. fp32 out.
__global__ void __launch_bounds__(256) prep_k(const float* __restrict__ zsrc,
                                              const float* __restrict__ csrc) {
    __shared__ float tile[32][129];   // [t][ch]
    __shared__ float sp[8][32];
    __shared__ float srn[32];

    int zz = blockIdx.y;
    bool is_c = zz >= Nn;
    int n = is_c ? zz - Nn : zz;
    int ld      = is_c ? (Ll + 1) : Ll;
    int col_off = is_c ? 1 : 0;
    int t0 = blockIdx.x * 32;
    const float* s = (is_c ? csrc : zsrc) + (size_t)n * Cc * ld + col_off + t0;
    float* d = (is_c ? g_cf : g_zf) + ((size_t)n * Ll + t0) * Cc;

    int tid = threadIdx.x;
    int tx  = tid & 31;    // t within tile
    int ty  = tid >> 5;    // 0..7

    // Load 16 channels for t=tx; accumulate sum-of-squares on the fly.
    float acc = 0.f;
#pragma unroll
    for (int i = 0; i < 16; i++) {
        int ch = i * 8 + ty;
        float v = s[(size_t)ch * ld + tx];
        tile[tx][ch] = v;
        acc += v * v;
    }
    sp[ty][tx] = acc;
    __syncthreads();

    if (tid < 32) {
        float sum = 0.f;
#pragma unroll
        for (int y = 0; y < 8; y++) sum += sp[y][tid];
        srn[tid] = 1.0f / fmaxf(sqrtf(sum), EPSf);
    }
    __syncthreads();

    // Write: 32 rows x 32 float4 = 1024 float4; 4 per thread, coalesced.
#pragma unroll
    for (int i = 0; i < 4; i++) {
        int linear = tid + i * 256;
        int t = linear >> 5;        // row within tile
        int k = linear & 31;        // float4 within row
        float rn = srn[t];
        float4 v;
        v.x = tile[t][k * 4 + 0] * rn;
        v.y = tile[t][k * 4 + 1] * rn;
        v.z = tile[t][k * 4 + 2] * rn;
        v.w = tile[t][k * 4 + 3] * rn;
        ((float4*)(d + (size_t)t * Cc))[k] = v;
    }
}

// Warp-per-row, 8 warps/block. 8 lanes per dot; lane p owns float4 slots
// p, 8+p, 16+p, 24+p -> each 8-lane group's LDG.128 covers one contiguous
// 128B line. 4 dots/pass, 26 passes. z double-buffered; index register kept
// 2 passes ahead (LDS from smem-staged indices) so there is no dependent
// global->global chain anywhere in the loop.
__global__ void __launch_bounds__(256, 4) main_k(const int* __restrict__ neg_inds,
                                                 float* __restrict__ out) {
    __shared__ int sidx[8][108];

    int warp = threadIdx.x >> 5;
    int r    = (blockIdx.x << 3) + warp;   // 0..N*L-1
    int n    = r >> 10;
    int t    = r & (Ll - 1);
    int lane = threadIdx.x & 31;
    int g    = lane >> 3;                  // dot slot within pass
    int p    = lane & 7;                   // lane within dot

    // Stage indices: slot 0 = t (positive), 1..100 = negatives, 101..107 = t.
    const int* ni = neg_inds + (size_t)r * Kk;
    int* si = sidx[warp];
#pragma unroll
    for (int i = 0; i < 4; i++) {
        int jj = lane + 32 * i;            // 0..127
        if (jj < 108) si[jj] = (jj >= 1 && jj <= Kk) ? ni[jj - 1] : t;
    }
    __syncwarp();

    // c chunk: 16 channels for this lane (slots p, 8+p, 16+p, 24+p).
    const float4* crow = (const float4*)(g_cf + (size_t)r * Cc);
    float4 c0 = crow[p], c1 = crow[8 + p], c2 = crow[16 + p], c3 = crow[24 + p];

    const float4* zbase = (const float4*)(g_zf + ((size_t)n << 10) * Cc);
    float*        orow  = out + (size_t)r * (Kk + 1);

    // Prologue: z for pass 0; index register for pass 1's prefetch.
    int ia = si[g];
    const float4* zr0 = zbase + (size_t)ia * 32;
    float4 z0 = zr0[p], z1 = zr0[8 + p], z2 = zr0[16 + p], z3 = zr0[24 + p];
    int inext = si[4 + g];

#pragma unroll
    for (int pass = 0; pass < 26; pass++) {
        int j = pass * 4 + g;

        // Prefetch z for pass+1 using already-resident index inext;
        // fetch (LDS) the index for pass+2.
        float4 y0, y1, y2, y3;
        if (pass < 25) {
            const float4* zr = zbase + (size_t)inext * 32;
            y0 = zr[p]; y1 = zr[8 + p]; y2 = zr[16 + p]; y3 = zr[24 + p];
        }
        if (pass < 24) inext = si[j + 8];

        float a = c0.x * z0.x + c0.y * z0.y + c0.z * z0.z + c0.w * z0.w;
        a += c1.x * z1.x + c1.y * z1.y + c1.z * z1.z + c1.w * z1.w;
        a += c2.x * z2.x + c2.y * z2.y + c2.z * z2.z + c2.w * z2.w;
        a += c3.x * z3.x + c3.y * z3.y + c3.z * z3.z + c3.w * z3.w;

        a += __shfl_xor_sync(0xffffffffu, a, 1);
        a += __shfl_xor_sync(0xffffffffu, a, 2);
        a += __shfl_xor_sync(0xffffffffu, a, 4);

        if (p == 0 && j <= Kk)
            orow[j] = a * 2.0f;   // norms folded in; / TEMP = *2

        z0 = y0; z1 = y1; z2 = y2; z3 = y3;
    }
}

extern "C" void kernel_launch(void* const* d_in, const int* in_sizes, int n_in,
                              void* d_out, int out_size) {
    const float* z  = (const float*)d_in[0];  // [N, C, L]
    const float* c  = (const float*)d_in[1];  // [N, C, L+1]
    const int*   ni = (const int*)d_in[2];    // [N, L, K]
    float* out = (float*)d_out;               // [N*L, K+1]

    dim3 pg(Ll / 32, 2 * Nn);
    prep_k<<<pg, 256>>>(z, c);

    main_k<<<(Nn * Ll) / 8, 256>>>(ni, out);
}

// round 11
// speedup vs baseline: 1.5529x; 1.5529x over previous
#include <cuda_runtime.h>
#include <cuda_fp16.h>
#include <cstdint>

#define Nn 8
#define Cc 128
#define Ll 1024
#define Kk 100
#define EPSf 1e-8f

// Normalized fp16 rows, [N, L, C] (256B per row).
__device__ __half g_zh[Nn * Ll * Cc];
__device__ __half g_ch[Nn * Ll * Cc];

// Fused: transpose + norm + normalize + fp16 convert, one pass over the input.
__global__ void __launch_bounds__(256) prep_k(const float* __restrict__ zsrc,
                                              const float* __restrict__ csrc) {
    __shared__ float tile[32][129];
    __shared__ float sp[8][32];
    __shared__ float srn[32];

    int zz = blockIdx.y;
    bool is_c = zz >= Nn;
    int n = is_c ? zz - Nn : zz;
    int ld      = is_c ? (Ll + 1) : Ll;
    int col_off = is_c ? 1 : 0;
    int t0 = blockIdx.x * 32;
    const float* s = (is_c ? csrc : zsrc) + (size_t)n * Cc * ld + col_off + t0;
    __half* d = (is_c ? g_ch : g_zh) + ((size_t)n * Ll + t0) * Cc;

    int tid = threadIdx.x;
    int tx  = tid & 31;
    int ty  = tid >> 5;

    float acc = 0.f;
#pragma unroll
    for (int i = 0; i < 16; i++) {
        int ch = i * 8 + ty;
        float v = s[(size_t)ch * ld + tx];
        tile[tx][ch] = v;
        acc += v * v;
    }
    sp[ty][tx] = acc;
    __syncthreads();

    if (tid < 32) {
        float sum = 0.f;
#pragma unroll
        for (int y = 0; y < 8; y++) sum += sp[y][tid];
        srn[tid] = 1.0f / fmaxf(sqrtf(sum), EPSf);
    }
    __syncthreads();

#pragma unroll
    for (int i = 0; i < 2; i++) {
        int linear = tid + i * 256;
        int t = linear >> 4;
        int k = linear & 15;
        float rn = srn[t];
        __half2 h[4];
#pragma unroll
        for (int q = 0; q < 4; q++) {
            float a = tile[t][k * 8 + 2 * q]     * rn;
            float b = tile[t][k * 8 + 2 * q + 1] * rn;
            h[q] = __floats2half2_rn(a, b);
        }
        ((uint4*)(d + (size_t)t * Cc))[k] = *(const uint4*)h;
    }
}

// Warp-per-row, 8 warps/block. 8 lanes per dot; lane p owns uint4 slots p and
// 8+p (one contiguous 128B line per 8-lane group per LDG).
// Indices smem-staged; z double-buffered with index kept one pass further
// ahead (no dependent global->global chain). Dot products computed with
// native HFMA2 (no per-element F2F conversions); only the final half2
// accumulator is widened to fp32 for the cross-lane reduction.
__global__ void __launch_bounds__(256) main_k(const int* __restrict__ neg_inds,
                                              float* __restrict__ out) {
    __shared__ int sidx[8][108];

    int warp = threadIdx.x >> 5;
    int r    = (blockIdx.x << 3) + warp;   // 0..N*L-1
    int n    = r >> 10;
    int t    = r & (Ll - 1);
    int lane = threadIdx.x & 31;
    int g    = lane >> 3;                  // dot slot within pass
    int p    = lane & 7;                   // lane within dot

    // Stage indices: slot 0 = t (positive), 1..100 = negatives, 101..107 = t.
    const int* ni = neg_inds + (size_t)r * Kk;
    int* si = sidx[warp];
#pragma unroll
    for (int i = 0; i < 4; i++) {
        int jj = lane + 32 * i;            // 0..127
        if (jj < 108) si[jj] = (jj >= 1 && jj <= Kk) ? ni[jj - 1] : t;
    }
    __syncwarp();

    // c chunk: 16 channels for this lane (slots p and 8+p), kept as half2.
    const uint4* crow = (const uint4*)(g_ch + (size_t)r * Cc);
    uint4 ca = crow[p], cb = crow[8 + p];
    __half2 ch2[8];
    {
        const __half2* h = (const __half2*)&ca;
        ch2[0] = h[0]; ch2[1] = h[1]; ch2[2] = h[2]; ch2[3] = h[3];
        h = (const __half2*)&cb;
        ch2[4] = h[0]; ch2[5] = h[1]; ch2[6] = h[2]; ch2[7] = h[3];
    }

    const uint4* zbase = (const uint4*)(g_zh + ((size_t)n << 10) * Cc);
    float*       orow  = out + (size_t)r * (Kk + 1);

    // Prologue: z for pass 0; index register for pass 1's prefetch.
    int ia = si[g];
    uint4 z0a = zbase[(size_t)ia * 16 + p];
    uint4 z0b = zbase[(size_t)ia * 16 + 8 + p];
    int inext = si[4 + g];

#pragma unroll
    for (int pass = 0; pass < 26; pass++) {
        int j = pass * 4 + g;

        // Prefetch z for pass+1 (index already resident); LDS index for pass+2.
        uint4 ya, yb;
        if (pass < 25) {
            ya = zbase[(size_t)inext * 16 + p];
            yb = zbase[(size_t)inext * 16 + 8 + p];
        }
        if (pass < 24) inext = si[j + 8];

        // 16 products via 8 HFMA2, accumulate in half2.
        __half2 acc = __floats2half2_rn(0.f, 0.f);
        {
            const __half2* zh = (const __half2*)&z0a;
            acc = __hfma2(ch2[0], zh[0], acc);
            acc = __hfma2(ch2[1], zh[1], acc);
            acc = __hfma2(ch2[2], zh[2], acc);
            acc = __hfma2(ch2[3], zh[3], acc);
            zh = (const __half2*)&z0b;
            acc = __hfma2(ch2[4], zh[0], acc);
            acc = __hfma2(ch2[5], zh[1], acc);
            acc = __hfma2(ch2[6], zh[2], acc);
            acc = __hfma2(ch2[7], zh[3], acc);
        }
        float2 f = __half22float2(acc);
        float a = f.x + f.y;

        a += __shfl_xor_sync(0xffffffffu, a, 1);
        a += __shfl_xor_sync(0xffffffffu, a, 2);
        a += __shfl_xor_sync(0xffffffffu, a, 4);

        if (p == 0 && j <= Kk)
            orow[j] = a * 2.0f;   // norms folded in; / TEMP = *2

        z0a = ya; z0b = yb;
    }
}

extern "C" void kernel_launch(void* const* d_in, const int* in_sizes, int n_in,
                              void* d_out, int out_size) {
    const float* z  = (const float*)d_in[0];  // [N, C, L]
    const float* c  = (const float*)d_in[1];  // [N, C, L+1]
    const int*   ni = (const int*)d_in[2];    // [N, L, K]
    float* out = (float*)d_out;               // [N*L, K+1]

    dim3 pg(Ll / 32, 2 * Nn);
    prep_k<<<pg, 256>>>(z, c);

    main_k<<<(Nn * Ll) / 8, 256>>>(ni, out);
}